// round 1
// baseline (speedup 1.0000x reference)
#include <cuda_runtime.h>
#include <math.h>

#define B      8192
#define T      20
#define NF     812
#define HID    400
#define G4     (4*HID)      // 1600
#define VAR    811
#define LDW    (NF+1)       // 813, W_ih row stride

#define BM 64
#define BN 64
#define BK 16

// ---------------- scratch (device globals; no allocations allowed) -------------
__device__ float d_pre[(size_t)B * T * G4];   // values @ W_ih[:, :812].T  (~1.05 GB)
__device__ float d_h[B * HID];
__device__ float d_c[B * HID];
__device__ float d_hdec[B * HID];
__device__ float d_gates[B * G4];
__device__ float d_xh[T * B];
__device__ float d_wsum[HID];
__device__ float d_wih_pack[G4 * NF];
__device__ float d_wv[G4];
__device__ float d_wm[G4];
__device__ float d_bsum[G4];
__device__ float d_steploss[T];

// ---------------- prep: pack W_ih, rowsum W_decay, zero state ------------------
__global__ void prep_kernel(const float* __restrict__ W_decay,
                            const float* __restrict__ W_ih,
                            const float* __restrict__ b_ih,
                            const float* __restrict__ b_hh)
{
    int idx = blockIdx.x * blockDim.x + threadIdx.x;
    int stride = gridDim.x * blockDim.x;

    for (int i = idx; i < G4 * NF; i += stride) {
        int g = i / NF, k = i - g * NF;
        d_wih_pack[i] = W_ih[g * LDW + k];
    }
    for (int i = idx; i < G4; i += stride) {
        d_wv[i]   = W_ih[i * LDW + VAR];
        d_wm[i]   = W_ih[i * LDW + NF];
        d_bsum[i] = b_ih[i] + b_hh[i];
    }
    for (int i = idx; i < HID; i += stride) {
        float s = 0.f;
        const float* row = W_decay + (size_t)i * NF;
        for (int k = 0; k < NF; k++) s += row[k];
        d_wsum[i] = s;
    }
    for (int i = idx; i < B * HID; i += stride) {
        d_h[i] = 0.f;
        d_c[i] = 0.f;
    }
}

// ---------------- generic GEMM: C[M,N] = A[M,K] @ Bmat[N,K]^T ------------------
// A row-major lda, Bmat row-major ldb, C row-major ldc. K predicated; M,N assumed
// multiples of tile (true for all call sites here), but guarded anyway.
__global__ void gemm_tn(const float* __restrict__ A, int lda,
                        const float* __restrict__ Bmat, int ldb,
                        float* __restrict__ C, int ldc,
                        int M, int N, int K)
{
    __shared__ float As[BK][BM + 4];
    __shared__ float Bs[BK][BN + 4];

    const int row0 = blockIdx.y * BM;
    const int col0 = blockIdx.x * BN;
    const int tid  = threadIdx.x;          // 256 threads
    const int la_r = tid >> 2;             // 0..63
    const int la_k = (tid & 3) * 4;        // 0,4,8,12
    const int tr   = tid / 16;             // 0..15
    const int tc   = tid % 16;             // 0..15

    float acc[4][4] = {};

    for (int k0 = 0; k0 < K; k0 += BK) {
        {
            int gr = row0 + la_r, gk = k0 + la_k;
            float4 v = make_float4(0.f, 0.f, 0.f, 0.f);
            if (gr < M && gk < K) v = *(const float4*)(A + (size_t)gr * lda + gk);
            As[la_k + 0][la_r] = v.x; As[la_k + 1][la_r] = v.y;
            As[la_k + 2][la_r] = v.z; As[la_k + 3][la_r] = v.w;
        }
        {
            int gn = col0 + la_r, gk = k0 + la_k;
            float4 v = make_float4(0.f, 0.f, 0.f, 0.f);
            if (gn < N && gk < K) v = *(const float4*)(Bmat + (size_t)gn * ldb + gk);
            Bs[la_k + 0][la_r] = v.x; Bs[la_k + 1][la_r] = v.y;
            Bs[la_k + 2][la_r] = v.z; Bs[la_k + 3][la_r] = v.w;
        }
        __syncthreads();

        #pragma unroll
        for (int kk = 0; kk < BK; kk++) {
            float4 av = *(const float4*)&As[kk][tr * 4];
            float4 bv = *(const float4*)&Bs[kk][tc * 4];
            float a[4] = {av.x, av.y, av.z, av.w};
            float b[4] = {bv.x, bv.y, bv.z, bv.w};
            #pragma unroll
            for (int i = 0; i < 4; i++)
                #pragma unroll
                for (int j = 0; j < 4; j++)
                    acc[i][j] += a[i] * b[j];
        }
        __syncthreads();
    }

    #pragma unroll
    for (int i = 0; i < 4; i++) {
        int r = row0 + tr * 4 + i;
        if (r >= M) continue;
        int c = col0 + tc * 4;
        if (c + 3 < N) {
            float4 v = make_float4(acc[i][0], acc[i][1], acc[i][2], acc[i][3]);
            *(float4*)(C + (size_t)r * ldc + c) = v;
        }
    }
}

// ---------------- decay: h_dec = h * gamma;  x_h = h_dec . W_reg + b_reg --------
__global__ void decay_kernel(int t,
                             const float* __restrict__ deltas,
                             const float* __restrict__ b_decay,
                             const float* __restrict__ W_reg,
                             const float* __restrict__ b_reg)
{
    __shared__ float sdata[128];
    const int b = blockIdx.x;
    const float d = deltas[b * T + t];
    float partial = 0.f;
    for (int h = threadIdx.x; h < HID; h += 128) {
        float z     = d * d_wsum[h] + b_decay[h];
        float gamma = expf(-fmaxf(z, 0.f));
        float hv    = d_h[b * HID + h] * gamma;
        d_hdec[b * HID + h] = hv;
        partial += hv * W_reg[h];
    }
    sdata[threadIdx.x] = partial;
    __syncthreads();
    for (int s = 64; s > 0; s >>= 1) {
        if (threadIdx.x < s) sdata[threadIdx.x] += sdata[threadIdx.x + s];
        __syncthreads();
    }
    if (threadIdx.x == 0) d_xh[t * B + b] = sdata[0] + b_reg[0];
}

// ---------------- LSTM pointwise update ----------------------------------------
__device__ __forceinline__ float sigf(float x) { return 1.f / (1.f + expf(-x)); }

__global__ void lstm_kernel(int t,
                            const float* __restrict__ values,
                            const float* __restrict__ masks)
{
    int idx = blockIdx.x * blockDim.x + threadIdx.x;   // over B*HID
    if (idx >= B * HID) return;
    int b = idx / HID, h = idx - b * HID;

    float m     = masks[b * T + t];
    float xr    = values[(size_t)(b * T + t) * NF + VAR];
    float xh    = d_xh[t * B + b];
    float alpha = (1.f - m) * (xh - xr);               // x_var - x_raw

    const size_t prerow = (size_t)(b * T + t) * G4;
    float g[4];
    #pragma unroll
    for (int q = 0; q < 4; q++) {
        int col = q * HID + h;
        g[q] = d_gates[b * G4 + col] + d_pre[prerow + col]
             + d_bsum[col] + alpha * d_wv[col] + m * d_wm[col];
    }
    float ig = sigf(g[0]);
    float fg = sigf(g[1]);
    float gg = tanhf(g[2]);
    float og = sigf(g[3]);
    float c  = fg * d_c[idx] + ig * gg;
    d_c[idx] = c;
    d_h[idx] = og * tanhf(c);
}

// ---------------- loss per step (deterministic reduction) ----------------------
__global__ void loss_kernel(const float* __restrict__ values,
                            const float* __restrict__ masks)
{
    __shared__ float snum[256];
    __shared__ float sden[256];
    const int t = blockIdx.x;
    float num = 0.f, den = 0.f;
    for (int b = threadIdx.x; b < B; b += 256) {
        float m  = masks[b * T + t];
        float xr = values[(size_t)(b * T + t) * NF + VAR];
        float xh = d_xh[t * B + b];
        num += m * fabsf(xr - xh);
        den += m;
    }
    snum[threadIdx.x] = num;
    sden[threadIdx.x] = den;
    __syncthreads();
    for (int s = 128; s > 0; s >>= 1) {
        if (threadIdx.x < s) {
            snum[threadIdx.x] += snum[threadIdx.x + s];
            sden[threadIdx.x] += sden[threadIdx.x + s];
        }
        __syncthreads();
    }
    if (threadIdx.x == 0) d_steploss[t] = snum[0] / (sden[0] + 1e-5f);
}

// ---------------- write outputs -------------------------------------------------
__global__ void writeout_kernel(const float* __restrict__ values,
                                const float* __restrict__ masks,
                                float* __restrict__ out, int out_size)
{
    int idx = blockIdx.x * blockDim.x + threadIdx.x;   // over B*T
    const int has_loss = (out_size > B * T) ? 1 : 0;
    if (idx < B * T) {
        int b = idx / T, t = idx - b * T;
        float m   = masks[idx];
        float xr  = values[(size_t)idx * NF + VAR];
        float xh  = d_xh[t * B + b];
        float imp = m * xr + (1.f - m) * xh;
        int o = has_loss + idx;
        if (o < out_size) out[o] = imp;
    }
    if (idx == 0 && has_loss) {
        float s = 0.f;
        for (int t = 0; t < T; t++) s += d_steploss[t];
        out[0] = s / (float)T;
    }
}

// ---------------- launch --------------------------------------------------------
extern "C" void kernel_launch(void* const* d_in, const int* in_sizes, int n_in,
                              void* d_out, int out_size)
{
    const float* values  = (const float*)d_in[0];
    const float* masks   = (const float*)d_in[1];
    const float* deltas  = (const float*)d_in[2];
    const float* W_decay = (const float*)d_in[3];
    const float* b_decay = (const float*)d_in[4];
    const float* W_reg   = (const float*)d_in[5];
    const float* b_reg   = (const float*)d_in[6];
    const float* W_ih    = (const float*)d_in[7];
    const float* W_hh    = (const float*)d_in[8];
    const float* b_ih    = (const float*)d_in[9];
    const float* b_hh    = (const float*)d_in[10];
    float* out = (float*)d_out;

    // resolve device-global addresses for GEMM args
    float *pre_p, *hdec_p, *gates_p, *pack_p;
    cudaGetSymbolAddress((void**)&pre_p,   d_pre);
    cudaGetSymbolAddress((void**)&hdec_p,  d_hdec);
    cudaGetSymbolAddress((void**)&gates_p, d_gates);
    cudaGetSymbolAddress((void**)&pack_p,  d_wih_pack);

    prep_kernel<<<4096, 256>>>(W_decay, W_ih, b_ih, b_hh);

    // pre = values[M=B*T, K=812] @ wih_pack[N=1600, K=812]^T
    {
        dim3 grid(G4 / BN, (B * T) / BM);
        gemm_tn<<<grid, 256>>>(values, NF, pack_p, NF, pre_p, G4, B * T, G4, NF);
    }

    for (int t = 0; t < T; t++) {
        decay_kernel<<<B, 128>>>(t, deltas, b_decay, W_reg, b_reg);
        dim3 grid(G4 / BN, B / BM);
        gemm_tn<<<grid, 256>>>(hdec_p, HID, W_hh, HID, gates_p, G4, B, G4, HID);
        lstm_kernel<<<(B * HID + 255) / 256, 256>>>(t, values, masks);
    }

    loss_kernel<<<T, 256>>>(values, masks);
    writeout_kernel<<<(B * T + 255) / 256, 256>>>(values, masks, out, out_size);
}

// round 3
// speedup vs baseline: 5.5862x; 5.5862x over previous
#include <cuda_runtime.h>
#include <cuda_fp16.h>
#include <math.h>
#include <stdint.h>

#define B_    8192
#define T_    20
#define MBT   163840        // B_*T_
#define NF    812
#define HID   400
#define G4    1600
#define NP    1664          // padded N (13 * 128)
#define VAR   811
#define LDW   813           // W_ih row stride in input

#define KPB   832           // padded K for big GEMM (26 * 32)
#define KPR   416           // padded K for recurrent GEMM (13 * 32)

#define BM    128
#define BN    128
#define BK    32
#define STAGE_BYTES 16384   // A 8KB + B 8KB
#define SMEM_DYN (3 * STAGE_BYTES)   // 48KB, no opt-in needed

// ---------------- device scratch ------------------------------------------------
__device__ __align__(128) float  d_pre[(size_t)MBT * NP];     // ~1.09 GB
__device__ __align__(128) float  d_gates[B_ * NP];
__device__ __align__(128) __half d_valh[(size_t)MBT * KPB];   // ~273 MB
__device__ __align__(128) __half d_wih_h[NP * KPB];
__device__ __align__(128) __half d_whh_h[NP * KPR];
__device__ __align__(128) __half d_hdech[B_ * KPR];
__device__ float d_h[B_ * HID];
__device__ float d_c[B_ * HID];
__device__ float d_xh[T_ * B_];
__device__ float d_wsum[HID];
__device__ float d_wv[G4];
__device__ float d_wm[G4];
__device__ float d_bsum[G4];
__device__ float d_steploss[T_];

// ---------------- portable PTX helpers -------------------------------------------
__device__ __forceinline__ void cp16(uint32_t saddr, const void* g) {
    asm volatile("cp.async.cg.shared.global [%0], [%1], 16;" :: "r"(saddr), "l"(g));
}
__device__ __forceinline__ void cp_commit() {
    asm volatile("cp.async.commit_group;" ::: "memory");
}
template <int N>
__device__ __forceinline__ void cp_wait() {
    asm volatile("cp.async.wait_group %0;" :: "n"(N) : "memory");
}
__device__ __forceinline__ void ldm_x4(uint32_t* r, uint32_t addr) {
    asm volatile("ldmatrix.sync.aligned.m8n8.x4.shared.b16 {%0,%1,%2,%3}, [%4];"
                 : "=r"(r[0]), "=r"(r[1]), "=r"(r[2]), "=r"(r[3]) : "r"(addr));
}
__device__ __forceinline__ uint32_t lds32(uint32_t addr) {
    uint32_t v;
    asm volatile("ld.shared.b32 %0, [%1];" : "=r"(v) : "r"(addr));
    return v;
}
__device__ __forceinline__ void mma16816(float* c, const uint32_t* a, const uint32_t* b) {
    asm volatile(
        "mma.sync.aligned.m16n8k16.row.col.f32.f16.f16.f32 "
        "{%0,%1,%2,%3}, {%4,%5,%6,%7}, {%8,%9}, {%0,%1,%2,%3};"
        : "+f"(c[0]), "+f"(c[1]), "+f"(c[2]), "+f"(c[3])
        : "r"(a[0]), "r"(a[1]), "r"(a[2]), "r"(a[3]), "r"(b[0]), "r"(b[1]));
}
__device__ __forceinline__ uint32_t swz(uint32_t off) {   // 64B-row swizzle
    return off ^ ((off >> 3) & 0x30);
}

// ---------------- HMMA GEMM: C[M, NP] = A[M,K] @ Bw[NP,K]^T ----------------------
// A fp16 [gridDim.y*128][ldA], Bw fp16 [NP][ldB], C fp32 stride NP. K = NK*32.
__global__ __launch_bounds__(256, 2)
void gemm_hmma(const __half* __restrict__ A, const __half* __restrict__ Bw,
               float* __restrict__ C, int ldA, int ldB, int NK)
{
    extern __shared__ __align__(128) char sm[];
    const uint32_t smbase = (uint32_t)__cvta_generic_to_shared(sm);

    const int tid  = threadIdx.x;
    const int lane = tid & 31;
    const int wid  = tid >> 5;
    const int wm0  = (wid >> 2) * 64;     // warp row offset (2 warp-rows)
    const int wn0  = (wid & 3) * 32;      // warp col offset (4 warp-cols)
    const int m0   = blockIdx.y * BM;
    const int n0   = blockIdx.x * BN;

    // load-lane decomposition: 512 16B-chunks per tile, 2 per thread
    const int ldRow0 = tid >> 2;          // chunk/4
    const int ldCh0  = tid & 3;
    const int ldRow1 = (tid + 256) >> 2;
    const int ldCh1  = (tid + 256) & 3;

    // ldmatrix A lane mapping
    const int aRow = lane & 15;
    const int aChk = lane >> 4;
    // B scalar-lds lane mapping
    const int bRow  = lane >> 2;
    const int bCol4 = (lane & 3) * 4;

    float acc[4][4][4] = {};

    auto load_stage = [&](int s, int kt) {
        uint32_t aB = smbase + s * STAGE_BYTES;
        uint32_t bB = aB + 8192;
        const __half* ga0 = A + (size_t)(m0 + ldRow0) * ldA + kt * BK + ldCh0 * 8;
        const __half* ga1 = A + (size_t)(m0 + ldRow1) * ldA + kt * BK + ldCh1 * 8;
        cp16(aB + swz(ldRow0 * 64 + ldCh0 * 16), ga0);
        cp16(aB + swz(ldRow1 * 64 + ldCh1 * 16), ga1);
        const __half* gb0 = Bw + (size_t)(n0 + ldRow0) * ldB + kt * BK + ldCh0 * 8;
        const __half* gb1 = Bw + (size_t)(n0 + ldRow1) * ldB + kt * BK + ldCh1 * 8;
        cp16(bB + swz(ldRow0 * 64 + ldCh0 * 16), gb0);
        cp16(bB + swz(ldRow1 * 64 + ldCh1 * 16), gb1);
    };

    // prologue: fill 3 stages
    for (int s = 0; s < 3; s++) {
        load_stage(s, s);
        cp_commit();
    }

    for (int kt = 0; kt < NK; kt++) {
        if (kt + 2 < NK)      cp_wait<2>();
        else if (kt + 1 < NK) cp_wait<1>();
        else                  cp_wait<0>();
        __syncthreads();

        const int s = kt % 3;
        uint32_t aB = smbase + s * STAGE_BYTES;
        uint32_t bB = aB + 8192;

        #pragma unroll
        for (int ks = 0; ks < 2; ks++) {
            uint32_t afr[4][4];
            #pragma unroll
            for (int mt = 0; mt < 4; mt++) {
                int row = wm0 + mt * 16 + aRow;
                ldm_x4(afr[mt], aB + swz(row * 64 + (ks * 2 + aChk) * 16));
            }
            uint32_t bfr[4][2];
            #pragma unroll
            for (int nt = 0; nt < 4; nt++) {
                int row = wn0 + nt * 8 + bRow;
                uint32_t sw = swz(row * 64 + ks * 32 + bCol4);
                bfr[nt][0] = lds32(bB + sw);
                bfr[nt][1] = lds32(bB + (sw ^ 16));
            }
            #pragma unroll
            for (int mt = 0; mt < 4; mt++)
                #pragma unroll
                for (int nt = 0; nt < 4; nt++)
                    mma16816(acc[mt][nt], afr[mt], bfr[nt]);
        }

        if (kt + 3 < NK) {
            __syncthreads();
            load_stage(s, kt + 3);
            cp_commit();
        }
    }

    // epilogue
    #pragma unroll
    for (int mt = 0; mt < 4; mt++) {
        int r0 = m0 + wm0 + mt * 16 + (lane >> 2);
        #pragma unroll
        for (int nt = 0; nt < 4; nt++) {
            int col = n0 + wn0 + nt * 8 + 2 * (lane & 3);
            float* p0 = C + (size_t)r0 * NP + col;
            float* p1 = C + (size_t)(r0 + 8) * NP + col;
            *(float2*)p0 = make_float2(acc[mt][nt][0], acc[mt][nt][1]);
            *(float2*)p1 = make_float2(acc[mt][nt][2], acc[mt][nt][3]);
        }
    }
}

// ---------------- conversions / prep ----------------------------------------------
__global__ void conv_values_kernel(const float* __restrict__ values)
{
    const int row = blockIdx.x;              // 0..MBT-1
    const float* src = values + (size_t)row * NF;
    __half* dst = d_valh + (size_t)row * KPB;
    for (int c = threadIdx.x; c < KPB; c += blockDim.x)
        dst[c] = (c < NF) ? __float2half_rn(src[c]) : __half(0.f);
}

__global__ void prep_kernel(const float* __restrict__ W_decay,
                            const float* __restrict__ W_ih,
                            const float* __restrict__ W_hh,
                            const float* __restrict__ b_ih,
                            const float* __restrict__ b_hh)
{
    int idx = blockIdx.x * blockDim.x + threadIdx.x;
    int stride = gridDim.x * blockDim.x;

    for (int i = idx; i < NP * KPB; i += stride) {
        int g = i / KPB, k = i - g * KPB;
        d_wih_h[i] = (g < G4 && k < NF) ? __float2half_rn(W_ih[g * LDW + k]) : __half(0.f);
    }
    for (int i = idx; i < NP * KPR; i += stride) {
        int g = i / KPR, k = i - g * KPR;
        d_whh_h[i] = (g < G4 && k < HID) ? __float2half_rn(W_hh[g * HID + k]) : __half(0.f);
    }
    for (int i = idx; i < B_ * KPR; i += stride) d_hdech[i] = __half(0.f);
    for (int i = idx; i < G4; i += stride) {
        d_wv[i]   = W_ih[i * LDW + VAR];
        d_wm[i]   = W_ih[i * LDW + NF];
        d_bsum[i] = b_ih[i] + b_hh[i];
    }
    for (int i = idx; i < HID; i += stride) {
        float s = 0.f;
        const float* row = W_decay + (size_t)i * NF;
        for (int k = 0; k < NF; k++) s += row[k];
        d_wsum[i] = s;
    }
    for (int i = idx; i < B_ * HID; i += stride) {
        d_h[i] = 0.f;
        d_c[i] = 0.f;
    }
}

// ---------------- decay: h_dec = h * gamma (fp16 out);  x_h = h_dec . W_reg -------
__global__ void decay_kernel(int t,
                             const float* __restrict__ deltas,
                             const float* __restrict__ b_decay,
                             const float* __restrict__ W_reg,
                             const float* __restrict__ b_reg)
{
    __shared__ float sdata[128];
    const int b = blockIdx.x;
    const float d = deltas[b * T_ + t];
    float partial = 0.f;
    for (int h = threadIdx.x; h < HID; h += 128) {
        float z     = d * d_wsum[h] + b_decay[h];
        float gamma = expf(-fmaxf(z, 0.f));
        float hv    = d_h[b * HID + h] * gamma;
        d_hdech[b * KPR + h] = __float2half_rn(hv);
        partial += hv * W_reg[h];
    }
    sdata[threadIdx.x] = partial;
    __syncthreads();
    for (int s = 64; s > 0; s >>= 1) {
        if (threadIdx.x < s) sdata[threadIdx.x] += sdata[threadIdx.x + s];
        __syncthreads();
    }
    if (threadIdx.x == 0) d_xh[t * B_ + b] = sdata[0] + b_reg[0];
}

// ---------------- LSTM pointwise update --------------------------------------------
__device__ __forceinline__ float sigf(float x) { return 1.f / (1.f + expf(-x)); }

__global__ void lstm_kernel(int t,
                            const float* __restrict__ values,
                            const float* __restrict__ masks)
{
    int idx = blockIdx.x * blockDim.x + threadIdx.x;   // over B*HID
    if (idx >= B_ * HID) return;
    int b = idx / HID, h = idx - b * HID;

    float m     = masks[b * T_ + t];
    float xr    = values[(size_t)(b * T_ + t) * NF + VAR];
    float xh    = d_xh[t * B_ + b];
    float alpha = (1.f - m) * (xh - xr);               // x_var - x_raw

    const size_t prerow = (size_t)(b * T_ + t) * NP;
    float g[4];
    #pragma unroll
    for (int q = 0; q < 4; q++) {
        int col = q * HID + h;
        g[q] = d_gates[(size_t)b * NP + col] + d_pre[prerow + col]
             + d_bsum[col] + alpha * d_wv[col] + m * d_wm[col];
    }
    float ig = sigf(g[0]);
    float fg = sigf(g[1]);
    float gg = tanhf(g[2]);
    float og = sigf(g[3]);
    float c  = fg * d_c[idx] + ig * gg;
    d_c[idx] = c;
    d_h[idx] = og * tanhf(c);
}

// ---------------- loss + writeout ----------------------------------------------------
__global__ void loss_kernel(const float* __restrict__ values,
                            const float* __restrict__ masks)
{
    __shared__ float snum[256];
    __shared__ float sden[256];
    const int t = blockIdx.x;
    float num = 0.f, den = 0.f;
    for (int b = threadIdx.x; b < B_; b += 256) {
        float m  = masks[b * T_ + t];
        float xr = values[(size_t)(b * T_ + t) * NF + VAR];
        float xh = d_xh[t * B_ + b];
        num += m * fabsf(xr - xh);
        den += m;
    }
    snum[threadIdx.x] = num;
    sden[threadIdx.x] = den;
    __syncthreads();
    for (int s = 128; s > 0; s >>= 1) {
        if (threadIdx.x < s) {
            snum[threadIdx.x] += snum[threadIdx.x + s];
            sden[threadIdx.x] += sden[threadIdx.x + s];
        }
        __syncthreads();
    }
    if (threadIdx.x == 0) d_steploss[t] = snum[0] / (sden[0] + 1e-5f);
}

__global__ void writeout_kernel(const float* __restrict__ values,
                                const float* __restrict__ masks,
                                float* __restrict__ out, int out_size)
{
    int idx = blockIdx.x * blockDim.x + threadIdx.x;   // over B*T
    const int has_loss = (out_size > B_ * T_) ? 1 : 0;
    if (idx < B_ * T_) {
        int b = idx / T_, t = idx - b * T_;
        float m   = masks[idx];
        float xr  = values[(size_t)idx * NF + VAR];
        float xh  = d_xh[t * B_ + b];
        float imp = m * xr + (1.f - m) * xh;
        int o = has_loss + idx;
        if (o < out_size) out[o] = imp;
    }
    if (idx == 0 && has_loss) {
        float s = 0.f;
        for (int t = 0; t < T_; t++) s += d_steploss[t];
        out[0] = s / (float)T_;
    }
}

// ---------------- launch --------------------------------------------------------------
extern "C" void kernel_launch(void* const* d_in, const int* in_sizes, int n_in,
                              void* d_out, int out_size)
{
    const float* values  = (const float*)d_in[0];
    const float* masks   = (const float*)d_in[1];
    const float* deltas  = (const float*)d_in[2];
    const float* W_decay = (const float*)d_in[3];
    const float* b_decay = (const float*)d_in[4];
    const float* W_reg   = (const float*)d_in[5];
    const float* b_reg   = (const float*)d_in[6];
    const float* W_ih    = (const float*)d_in[7];
    const float* W_hh    = (const float*)d_in[8];
    const float* b_ih    = (const float*)d_in[9];
    const float* b_hh    = (const float*)d_in[10];
    float* out = (float*)d_out;

    float  *pre_p, *gates_p;
    __half *valh_p, *wih_p, *whh_p, *hdech_p;
    cudaGetSymbolAddress((void**)&pre_p,   d_pre);
    cudaGetSymbolAddress((void**)&gates_p, d_gates);
    cudaGetSymbolAddress((void**)&valh_p,  d_valh);
    cudaGetSymbolAddress((void**)&wih_p,   d_wih_h);
    cudaGetSymbolAddress((void**)&whh_p,   d_whh_h);
    cudaGetSymbolAddress((void**)&hdech_p, d_hdech);

    conv_values_kernel<<<MBT, 256>>>(values);
    prep_kernel<<<4096, 256>>>(W_decay, W_ih, W_hh, b_ih, b_hh);

    // pre[MBT, NP] = valh @ wih_h^T   (K = 832 -> 26 k-tiles)
    {
        dim3 grid(NP / BN, MBT / BM);
        gemm_hmma<<<grid, 256, SMEM_DYN>>>(valh_p, wih_p, pre_p, KPB, KPB, KPB / BK);
    }

    for (int t = 0; t < T_; t++) {
        decay_kernel<<<B_, 128>>>(t, deltas, b_decay, W_reg, b_reg);
        dim3 grid(NP / BN, B_ / BM);
        gemm_hmma<<<grid, 256, SMEM_DYN>>>(hdech_p, whh_p, gates_p, KPR, KPR, KPR / BK);
        lstm_kernel<<<(B_ * HID + 255) / 256, 256>>>(t, values, masks);
    }

    loss_kernel<<<T_, 256>>>(values, masks);
    writeout_kernel<<<(B_ * T_ + 255) / 256, 256>>>(values, masks, out, out_size);
}